// round 15
// baseline (speedup 1.0000x reference)
#include <cuda_runtime.h>
#include <cuda_fp16.h>
#include <cstdint>

#define B_ 256
#define T_ 512
#define H_ 512
#define O_ 16
#define NTHR 256
#define CLX 8
#define GRID_Y 16          // 16 batch-group PAIRS; each CTA runs 2 groups of 8

#define KTOT 576           // 0..511 = h/W_hh, 512..575 = x/W_ih
#define KH   288           // k per half (per-warp k-slice)
#define KS   18            // k16 steps per half

#define PITCHB 1168        // stage row pitch bytes (584 f16): conflict-free ldsm
#define SM_ST  0           // A stage: 16 rows x 1168 B (rows 0-7 hi, 8-15 lo)
#define SM_R   18688       // split-K partials: 4*32*2 float2 = 2048
#define SM_MB  20736       // 2 mbarriers (8B each)
#define SMEM_BYTES 20864

#define SC 2048.0f
#define INV_SC 4.8828125e-4f
#define X_ELEMS (256u * 512u * 64u)

// f16 exchange (hi / scaled-lo), ping-pong; x split; final h
__device__ __half g_hHi[2][B_][H_];
__device__ __half g_hLo[2][B_][H_];
__device__ __half g_xHi[(size_t)B_ * T_ * 64];
__device__ __half g_xLo[(size_t)B_ * T_ * 64];
__device__ float  g_hfin[B_ * H_];

// ---------------- helpers ----------------
__device__ __forceinline__ uint32_t smem_u32(const void* p) {
    uint32_t a;
    asm("{ .reg .u64 t; cvta.to.shared.u64 t, %1; cvt.u32.u64 %0, t; }" : "=r"(a) : "l"(p));
    return a;
}
__device__ __forceinline__ void mma16816(float* d, const uint32_t* a, const uint32_t* b) {
    asm volatile(
        "mma.sync.aligned.m16n8k16.row.col.f32.f16.f16.f32 "
        "{%0,%1,%2,%3}, {%4,%5,%6,%7}, {%8,%9}, {%0,%1,%2,%3};"
        : "+f"(d[0]), "+f"(d[1]), "+f"(d[2]), "+f"(d[3])
        : "r"(a[0]), "r"(a[1]), "r"(a[2]), "r"(a[3]), "r"(b[0]), "r"(b[1]));
}
__device__ __forceinline__ void ldsm4(uint32_t* a, uint32_t addr) {
    asm volatile("ldmatrix.sync.aligned.m8n8.x4.shared.b16 {%0,%1,%2,%3}, [%4];"
                 : "=r"(a[0]), "=r"(a[1]), "=r"(a[2]), "=r"(a[3]) : "r"(addr));
}
__device__ __forceinline__ uint32_t pack_hilo(float v0, float v1, uint32_t& lo) {
    __half h0 = __float2half_rn(v0), h1 = __float2half_rn(v1);
    __half l0 = __float2half_rn((v0 - __half2float(h0)) * SC);
    __half l1 = __float2half_rn((v1 - __half2float(h1)) * SC);
    __half2 lp = __halves2half2(l0, l1);
    lo = *reinterpret_cast<uint32_t*>(&lp);
    __half2 hp = __halves2half2(h0, h1);
    return *reinterpret_cast<uint32_t*>(&hp);
}
#define MBAR_INIT(mb, n) asm volatile("mbarrier.init.shared.b64 [%0], %1;" \
    :: "r"((uint32_t)(mb)), "r"((uint32_t)(n)) : "memory")
// arrive on rank's copy of this SMEM mbar (release, cluster scope)
#define MBAR_ARRIVE_CL(mb, rank) asm volatile( \
    "{ .reg .b32 ra; mapa.shared::cluster.u32 ra, %0, %1; " \
    "mbarrier.arrive.shared::cluster.b64 _, [ra]; }" \
    :: "r"((uint32_t)(mb)), "r"((uint32_t)(rank)) : "memory")
#define MBAR_WAIT_CL(mb, ph) do { uint32_t _d = 0; uint32_t _m = (mb); uint32_t _p = (ph); \
    while (!_d) { asm volatile( \
        "{ .reg .pred p; mbarrier.try_wait.parity.acquire.cluster.shared::cta.b64 p, [%1], %2; " \
        "selp.b32 %0,1,0,p; }" : "=r"(_d) : "r"(_m), "r"(_p) : "memory"); } } while (0)

// ---------------- pre-kernel: split x and h0 into f16 hi / scaled-lo ----------------
__global__ void __launch_bounds__(256) presplit_kernel(const float* __restrict__ x,
                                                       const float* __restrict__ h0) {
    size_t e = ((size_t)blockIdx.x * 256 + threadIdx.x) * 4;
    if (e < X_ELEMS) {
        float4 v = *(const float4*)(x + e);
        uint32_t lo0, lo1;
        uint32_t hi0 = pack_hilo(v.x, v.y, lo0);
        uint32_t hi1 = pack_hilo(v.z, v.w, lo1);
        *(uint2*)&g_xHi[e] = make_uint2(hi0, hi1);
        *(uint2*)&g_xLo[e] = make_uint2(lo0, lo1);
    } else {
        size_t e2 = e - X_ELEMS;
        if (e2 < (size_t)B_ * H_) {
            float4 v = *(const float4*)(h0 + e2);
            uint32_t lo0, lo1;
            uint32_t hi0 = pack_hilo(v.x, v.y, lo0);
            uint32_t hi1 = pack_hilo(v.z, v.w, lo1);
            *(uint2*)&g_hHi[0][0][e2] = make_uint2(hi0, hi1);
            *(uint2*)&g_hLo[0][0][e2] = make_uint2(lo0, lo1);
        }
    }
}

// ---------------- main persistent RNN kernel (dual-group interleave) ----------------
__global__ void __launch_bounds__(NTHR, 1) __cluster_dims__(CLX, 1, 1)
rnn_kernel(const float* __restrict__ Whh, const float* __restrict__ Wih,
           const float* __restrict__ bih, const float* __restrict__ bhh,
           const float* __restrict__ Wfc, const float* __restrict__ bfc,
           float* __restrict__ out, int out_size) {
    extern __shared__ char smem[];
    const uint32_t st_b = smem_u32(smem + SM_ST);
    const uint32_t mb0  = smem_u32(smem + SM_MB);       // group 0 mbar
    const uint32_t mb1  = mb0 + 8;                      // group 1 mbar
    float2* rbuf = (float2*)(smem + SM_R);

    const int tid = threadIdx.x, lane = tid & 31, warp = tid >> 5;
    const int ng = warp & 3;          // n-group: j0 = ng*16
    const int kh = warp >> 2;         // k-half
    const int jcb = blockIdx.x, bgp = blockIdx.y;
    const int hc0 = jcb * 64;
    const int bbA = bgp * 16, bbB = bgp * 16 + 8;

    // ---- mbarrier init (count 8 = one arrive per cluster CTA) + cluster sync ----
    if (tid == 0) { MBAR_INIT(mb0, 8); MBAR_INIT(mb1, 8); }
    __syncthreads();
    asm volatile("barrier.cluster.arrive.aligned;" ::: "memory");

    // ---- One-time: B fragments (W hi, f16) into registers ----
    uint32_t bfrag[2][KS][2];
    #pragma unroll
    for (int nf = 0; nf < 2; nf++) {
        const int jB = hc0 + ng * 16 + nf * 8 + (lane >> 2);
        #pragma unroll
        for (int ks = 0; ks < KS; ks++) {
            #pragma unroll
            for (int r = 0; r < 2; r++) {
                int kb = kh * KH + ks * 16 + (lane & 3) * 2 + r * 8;
                float2 w = (kb < 512)
                    ? *(const float2*)&Whh[(size_t)jB * 512 + kb]
                    : *(const float2*)&Wih[(size_t)jB * 64 + (kb - 512)];
                __half2 h2 = __floats2half2_rn(w.x, w.y);
                bfrag[nf][ks][r] = *reinterpret_cast<uint32_t*>(&h2);
            }
        }
    }

    // Epilogue constants
    const int bl0 = lane >> 2;
    int jj[2];
    float2 bias[2];
    #pragma unroll
    for (int nf = 0; nf < 2; nf++) {
        jj[nf] = hc0 + ng * 16 + nf * 8 + (lane & 3) * 2;
        bias[nf] = make_float2(bih[jj[nf]] + bhh[jj[nf]], bih[jj[nf] + 1] + bhh[jj[nf] + 1]);
    }

    int out_off = -1, h_off = -1;
    if (out_size >= B_ * O_ + B_ * H_)      { out_off = 0; h_off = B_ * O_; }
    else if (out_size == B_ * O_)           { out_off = 0; }
    else if (out_size == B_ * H_)           { h_off = 0; }
    else                                    { out_off = 0; }

    const uint32_t la = st_b + (lane & 15) * PITCHB + ((lane >> 4) * 8 + kh * KH) * 2;
    const int srow = warp;

    asm volatile("barrier.cluster.wait.aligned;" ::: "memory");   // inits visible

    for (int t = 0; t < T_; t++) {
        const int ping = t & 1, pong = ping ^ 1;
        const uint32_t par = (uint32_t)((t + 1) & 1);

        #pragma unroll
        for (int gsel = 0; gsel < 2; gsel++) {
            const int bb = gsel ? bbB : bbA;
            const uint32_t mb = gsel ? mb1 : mb0;

            if (t > 0) MBAR_WAIT_CL(mb, par);

            // ---- stage h (front-batched) + x ----
            {
                const uint4* sh = (const uint4*)&g_hHi[ping][bb + srow][0];
                const uint4* sl = (const uint4*)&g_hLo[ping][bb + srow][0];
                uint4 qa = __ldcg(sh + lane * 2), qb = __ldcg(sh + lane * 2 + 1);
                uint4 qc = __ldcg(sl + lane * 2), qd = __ldcg(sl + lane * 2 + 1);
                uint32_t xh = *(const uint32_t*)
                    &g_xHi[((size_t)(bb + srow) * T_ + t) * 64 + lane * 2];
                uint32_t xl = *(const uint32_t*)
                    &g_xLo[((size_t)(bb + srow) * T_ + t) * 64 + lane * 2];
                char* dh = smem + SM_ST + srow * PITCHB;
                char* dl = smem + SM_ST + (srow + 8) * PITCHB;
                *(uint4*)(dh + lane * 32) = qa; *(uint4*)(dh + lane * 32 + 16) = qb;
                *(uint4*)(dl + lane * 32) = qc; *(uint4*)(dl + lane * 32 + 16) = qd;
                *(uint32_t*)(dh + 1024 + lane * 4) = xh;
                *(uint32_t*)(dl + 1024 + lane * 4) = xl;
            }
            __syncthreads();

            // ---- mma over this warp's k-half (B from registers) ----
            float Dm[2][4] = {{0, 0, 0, 0}, {0, 0, 0, 0}};
            #pragma unroll
            for (int ks = 0; ks < KS; ks++) {
                uint32_t a[4];
                ldsm4(a, la + ks * 32);
                mma16816(Dm[0], a, bfrag[0][ks]);
                mma16816(Dm[1], a, bfrag[1][ks]);
            }
            float2 pr[2];
            #pragma unroll
            for (int nf = 0; nf < 2; nf++)
                pr[nf] = make_float2(Dm[nf][0] + Dm[nf][2] * INV_SC,
                                     Dm[nf][1] + Dm[nf][3] * INV_SC);

            if (kh == 1) {
                #pragma unroll
                for (int nf = 0; nf < 2; nf++)
                    rbuf[(ng * 32 + lane) * 2 + nf] = pr[nf];
            }
            __syncthreads();

            // ---- epilogue (kh==0): merge halves, +bias, relu, split, store ----
            if (kh == 0) {
                #pragma unroll
                for (int nf = 0; nf < 2; nf++) {
                    float2 p = rbuf[(ng * 32 + lane) * 2 + nf];
                    float v0 = fmaxf(pr[nf].x + p.x + bias[nf].x, 0.f);
                    float v1 = fmaxf(pr[nf].y + p.y + bias[nf].y, 0.f);
                    uint32_t lo0;
                    uint32_t hi0 = pack_hilo(v0, v1, lo0);
                    *(uint32_t*)&g_hHi[pong][bb + bl0][jj[nf]] = hi0;
                    *(uint32_t*)&g_hLo[pong][bb + bl0][jj[nf]] = lo0;
                    if (t == T_ - 1) {
                        *(float2*)&g_hfin[(size_t)(bb + bl0) * H_ + jj[nf]] = make_float2(v0, v1);
                        if (h_off >= 0)
                            *(float2*)&out[h_off + (size_t)(bb + bl0) * H_ + jj[nf]] =
                                make_float2(v0, v1);
                    }
                }
            }
            __syncthreads();   // all stores done before publishing

            if (tid < CLX) MBAR_ARRIVE_CL(mb, tid);
        }
    }

    // final wait: peers' last stores visible (phase 511 -> parity 1)
    MBAR_WAIT_CL(mb0, 1u);
    MBAR_WAIT_CL(mb1, 1u);
    __syncthreads();

    // ================= fused FC epilogue (2 batches per CTA) =================
    if (out_off >= 0) {
        const int myb0 = bgp * 16 + jcb * 2;
        float* hs = (float*)smem;    // reuse: [2][512] fp32
        for (int u = tid; u < 2 * H_; u += NTHR) {
            int b = u >> 9, k = u & 511;
            hs[u] = __ldcg(&g_hfin[(size_t)(myb0 + b) * H_ + k]);
        }
        __syncthreads();
        int w = tid >> 5, ln = tid & 31;
        if (w < 8) {
            int b  = w >> 2;
            int ob = (w & 3) << 2;
            #pragma unroll
            for (int oo = 0; oo < 4; oo++) {
                int o = ob + oo;
                float s = 0.f;
                #pragma unroll 4
                for (int k = ln; k < H_; k += 32)
                    s += hs[b * H_ + k] * Wfc[(size_t)o * H_ + k];
                #pragma unroll
                for (int d = 16; d > 0; d >>= 1)
                    s += __shfl_down_sync(0xFFFFFFFFu, s, d);
                if (ln == 0)
                    out[out_off + (size_t)(myb0 + b) * O_ + o] = s + bfc[o];
            }
        }
    }
}

extern "C" void kernel_launch(void* const* d_in, const int* in_sizes, int n_in,
                              void* d_out, int out_size) {
    const float* x    = (const float*)d_in[0];
    const float* h0   = (const float*)d_in[1];
    const float* W_ih = (const float*)d_in[2];
    const float* W_hh = (const float*)d_in[3];
    const float* b_ih = (const float*)d_in[4];
    const float* b_hh = (const float*)d_in[5];
    const float* W_fc = (const float*)d_in[6];
    const float* b_fc = (const float*)d_in[7];
    float* out = (float*)d_out;

    cudaFuncSetAttribute(rnn_kernel,
                         cudaFuncAttributeMaxDynamicSharedMemorySize, SMEM_BYTES);

    presplit_kernel<<<8320, 256>>>(x, h0);
    rnn_kernel<<<dim3(CLX, GRID_Y), NTHR, SMEM_BYTES>>>(W_hh, W_ih, b_ih, b_hh,
                                                        W_fc, b_fc, out, out_size);
}